// round 14
// baseline (speedup 1.0000x reference)
#include <cuda_runtime.h>
#include <cuda_bf16.h>
#include <cstdint>

#define BSZ 2
#define SEQ 2048
#define EMB 1024
#define NH  16
#define HD  64
#define MROWS (BSZ*SEQ)   // 4096

// ---------------------------------------------------------------------------
// Global scratch
// ---------------------------------------------------------------------------
__device__ __nv_bfloat16 g_xh[(size_t)MROWS * EMB];              // x split hi
__device__ __nv_bfloat16 g_xl[(size_t)MROWS * EMB];              // x split lo
__device__ __nv_bfloat16 g_wth[(size_t)3 * EMB * EMB];           // W^T split hi  [which][n][k]
__device__ __nv_bfloat16 g_wtl[(size_t)3 * EMB * EMB];           // W^T split lo
__device__ __nv_bfloat16 g_qkvh[(size_t)3 * MROWS * EMB];        // Q,K,V bf16 hi
__device__ __nv_bfloat16 g_qkvl[(size_t)3 * MROWS * EMB];        // Q,K,V bf16 lo

// ---------------------------------------------------------------------------
// PTX helpers
// ---------------------------------------------------------------------------
__device__ __forceinline__ uint32_t smem_u32(const void* p) {
    uint32_t a;
    asm("{ .reg .u64 t; cvta.to.shared.u64 t, %1; cvt.u32.u64 %0, t; }" : "=r"(a) : "l"(p));
    return a;
}
__device__ __forceinline__ void ldsm_x4(uint32_t* r, uint32_t addr) {
    asm volatile("ldmatrix.sync.aligned.m8n8.x4.shared.b16 {%0,%1,%2,%3}, [%4];"
                 : "=r"(r[0]), "=r"(r[1]), "=r"(r[2]), "=r"(r[3]) : "r"(addr));
}
__device__ __forceinline__ void ldsm_x4_t(uint32_t* r, uint32_t addr) {
    asm volatile("ldmatrix.sync.aligned.m8n8.x4.trans.shared.b16 {%0,%1,%2,%3}, [%4];"
                 : "=r"(r[0]), "=r"(r[1]), "=r"(r[2]), "=r"(r[3]) : "r"(addr));
}
__device__ __forceinline__ void mma16816(float* c, const uint32_t* a, uint32_t b0, uint32_t b1) {
    asm volatile("mma.sync.aligned.m16n8k16.row.col.f32.bf16.bf16.f32 "
                 "{%0,%1,%2,%3}, {%4,%5,%6,%7}, {%8,%9}, {%0,%1,%2,%3};"
                 : "+f"(c[0]), "+f"(c[1]), "+f"(c[2]), "+f"(c[3])
                 : "r"(a[0]), "r"(a[1]), "r"(a[2]), "r"(a[3]), "r"(b0), "r"(b1));
}
__device__ __forceinline__ void cpa16(uint32_t s, const void* g) {
    asm volatile("cp.async.cg.shared.global [%0], [%1], 16;" :: "r"(s), "l"(g));
}
#define CP_COMMIT() asm volatile("cp.async.commit_group;" ::: "memory")
#define CP_WAIT0()  asm volatile("cp.async.wait_group 0;" ::: "memory")
#define CP_WAIT1()  asm volatile("cp.async.wait_group 1;" ::: "memory")

__device__ __forceinline__ uint32_t pack_hi(float x, float y) {
    __nv_bfloat162 t(__float2bfloat16_rn(x), __float2bfloat16_rn(y));
    return *(uint32_t*)&t;
}
__device__ __forceinline__ uint32_t pack_lo(float x, float y, uint32_t hi) {
    __nv_bfloat162 hv = *(__nv_bfloat162*)&hi;
    __nv_bfloat162 t(__float2bfloat16_rn(x - __bfloat162float(hv.x)),
                     __float2bfloat16_rn(y - __bfloat162float(hv.y)));
    return *(uint32_t*)&t;
}

// ---------------------------------------------------------------------------
// Split x into bf16 hi/lo
// ---------------------------------------------------------------------------
__global__ __launch_bounds__(256) void split_x_kernel(const float* __restrict__ x) {
    const size_t n4 = (size_t)MROWS * EMB / 4;
    const float4* __restrict__ x4 = (const float4*)x;
    for (size_t i = blockIdx.x * 256 + threadIdx.x; i < n4; i += (size_t)gridDim.x * 256) {
        float4 v = x4[i];
        __nv_bfloat16 h0 = __float2bfloat16_rn(v.x);
        __nv_bfloat16 h1 = __float2bfloat16_rn(v.y);
        __nv_bfloat16 h2 = __float2bfloat16_rn(v.z);
        __nv_bfloat16 h3 = __float2bfloat16_rn(v.w);
        __nv_bfloat16 l0 = __float2bfloat16_rn(v.x - __bfloat162float(h0));
        __nv_bfloat16 l1 = __float2bfloat16_rn(v.y - __bfloat162float(h1));
        __nv_bfloat16 l2 = __float2bfloat16_rn(v.z - __bfloat162float(h2));
        __nv_bfloat16 l3 = __float2bfloat16_rn(v.w - __bfloat162float(h3));
        __nv_bfloat162* ph = (__nv_bfloat162*)&g_xh[i * 4];
        __nv_bfloat162* pl = (__nv_bfloat162*)&g_xl[i * 4];
        ph[0] = __nv_bfloat162(h0, h1); ph[1] = __nv_bfloat162(h2, h3);
        pl[0] = __nv_bfloat162(l0, l1); pl[1] = __nv_bfloat162(l2, l3);
    }
}

// ---------------------------------------------------------------------------
// Transpose + split W -> W^T hi/lo
// ---------------------------------------------------------------------------
__global__ __launch_bounds__(256) void split_wt_kernel(
    const float* __restrict__ Wq, const float* __restrict__ Wk, const float* __restrict__ Wv)
{
    const int which = blockIdx.z;
    const float* __restrict__ W = (which == 0) ? Wq : ((which == 1) ? Wk : Wv);
    __shared__ float tile[32][33];

    const int tx = threadIdx.x, ty = threadIdx.y;
    const int nt = blockIdx.x, kt = blockIdx.y;

#pragma unroll
    for (int i = 0; i < 4; i++) {
        int k = kt * 32 + ty + i * 8;
        tile[ty + i * 8][tx] = W[(size_t)k * EMB + nt * 32 + tx];
    }
    __syncthreads();

    const size_t base = (size_t)which * EMB * EMB;
#pragma unroll
    for (int i = 0; i < 4; i++) {
        int n = nt * 32 + ty + i * 8;
        int k = kt * 32 + tx;
        float v = tile[tx][ty + i * 8];
        __nv_bfloat16 h = __float2bfloat16_rn(v);
        __nv_bfloat16 l = __float2bfloat16_rn(v - __bfloat162float(h));
        g_wth[base + (size_t)n * EMB + k] = h;
        g_wtl[base + (size_t)n * EMB + k] = l;
    }
}

// ---------------------------------------------------------------------------
// Raw-mma QKV GEMM with cp.async 2-stage pipeline (R12 known-good).
// ---------------------------------------------------------------------------
#define TLD 40                      // smem row stride (elements); 80 bytes
#define BUF_B (128 * TLD * 2)       // 10240 bytes per buffer
#define STAGE_B (4 * BUF_B)         // 40960 per stage
#define OUT_LD 132
#define GT_SMEM_TOTAL (2 * STAGE_B) // 81920

__global__ __launch_bounds__(256) void qkv_gemm_mma_kernel(
    const float* __restrict__ bq, const float* __restrict__ bk, const float* __restrict__ bv)
{
    extern __shared__ char smem[];
    const uint32_t sb = smem_u32(smem);

    const int which = blockIdx.z;
    const int n0 = blockIdx.x * 128;
    const int m0 = blockIdx.y * 128;
    const float* __restrict__ bias = (which == 0) ? bq : ((which == 1) ? bk : bv);
    __nv_bfloat16* __restrict__ outh = g_qkvh + (size_t)which * MROWS * EMB;
    __nv_bfloat16* __restrict__ outl = g_qkvl + (size_t)which * MROWS * EMB;

    const int t    = threadIdx.x;
    const int w    = t / 32;
    const int lane = t % 32;
    const int wm   = w % 4;
    const int wn   = w / 4;
    const int g    = lane >> 2;
    const int tig  = lane & 3;

    const __nv_bfloat16* __restrict__ srcAh = g_xh + (size_t)m0 * EMB;
    const __nv_bfloat16* __restrict__ srcAl = g_xl + (size_t)m0 * EMB;
    const __nv_bfloat16* __restrict__ srcBh = g_wth + (size_t)which * EMB * EMB + (size_t)n0 * EMB;
    const __nv_bfloat16* __restrict__ srcBl = g_wtl + (size_t)which * EMB * EMB + (size_t)n0 * EMB;

    const int arow_off = (lane & 7) + ((lane >> 3) & 1) * 8;
    const int abyte    = (lane >> 4) * 16;
    const int brow_off = (lane & 7) + ((lane >> 4) & 1) * 8;
    const int bbyte    = ((lane >> 3) & 1) * 16;

    const int lrow0 = (t + 0)   / 4, lc0 = (t + 0)   % 4;
    const int lrow1 = (t + 256) / 4, lc1 = (t + 256) % 4;

    float acc[2][8][4];
#pragma unroll
    for (int i = 0; i < 2; i++)
#pragma unroll
        for (int j = 0; j < 8; j++)
#pragma unroll
            for (int e = 0; e < 4; e++) acc[i][j][e] = 0.0f;

    {
        uint32_t s0 = sb;
        cpa16(s0 + 0 * BUF_B + lrow0 * 80 + lc0 * 16, srcAh + (size_t)lrow0 * EMB + lc0 * 8);
        cpa16(s0 + 0 * BUF_B + lrow1 * 80 + lc1 * 16, srcAh + (size_t)lrow1 * EMB + lc1 * 8);
        cpa16(s0 + 1 * BUF_B + lrow0 * 80 + lc0 * 16, srcAl + (size_t)lrow0 * EMB + lc0 * 8);
        cpa16(s0 + 1 * BUF_B + lrow1 * 80 + lc1 * 16, srcAl + (size_t)lrow1 * EMB + lc1 * 8);
        cpa16(s0 + 2 * BUF_B + lrow0 * 80 + lc0 * 16, srcBh + (size_t)lrow0 * EMB + lc0 * 8);
        cpa16(s0 + 2 * BUF_B + lrow1 * 80 + lc1 * 16, srcBh + (size_t)lrow1 * EMB + lc1 * 8);
        cpa16(s0 + 3 * BUF_B + lrow0 * 80 + lc0 * 16, srcBl + (size_t)lrow0 * EMB + lc0 * 8);
        cpa16(s0 + 3 * BUF_B + lrow1 * 80 + lc1 * 16, srcBl + (size_t)lrow1 * EMB + lc1 * 8);
        CP_COMMIT();
    }

    for (int kc32 = 0; kc32 < EMB / 32; kc32++) {
        CP_WAIT0();
        __syncthreads();

        if (kc32 + 1 < EMB / 32) {
            const int kc = (kc32 + 1) * 32;
            uint32_t s1 = sb + ((kc32 + 1) & 1) * STAGE_B;
            cpa16(s1 + 0 * BUF_B + lrow0 * 80 + lc0 * 16, srcAh + (size_t)lrow0 * EMB + kc + lc0 * 8);
            cpa16(s1 + 0 * BUF_B + lrow1 * 80 + lc1 * 16, srcAh + (size_t)lrow1 * EMB + kc + lc1 * 8);
            cpa16(s1 + 1 * BUF_B + lrow0 * 80 + lc0 * 16, srcAl + (size_t)lrow0 * EMB + kc + lc0 * 8);
            cpa16(s1 + 1 * BUF_B + lrow1 * 80 + lc1 * 16, srcAl + (size_t)lrow1 * EMB + kc + lc1 * 8);
            cpa16(s1 + 2 * BUF_B + lrow0 * 80 + lc0 * 16, srcBh + (size_t)lrow0 * EMB + kc + lc0 * 8);
            cpa16(s1 + 2 * BUF_B + lrow1 * 80 + lc1 * 16, srcBh + (size_t)lrow1 * EMB + kc + lc1 * 8);
            cpa16(s1 + 3 * BUF_B + lrow0 * 80 + lc0 * 16, srcBl + (size_t)lrow0 * EMB + kc + lc0 * 8);
            cpa16(s1 + 3 * BUF_B + lrow1 * 80 + lc1 * 16, srcBl + (size_t)lrow1 * EMB + kc + lc1 * 8);
            CP_COMMIT();
        }

        const uint32_t st = sb + (kc32 & 1) * STAGE_B;
        const uint32_t aH = st + 0 * BUF_B;
        const uint32_t bH = st + 2 * BUF_B;

#pragma unroll
        for (int k16 = 0; k16 < 2; k16++) {
            uint32_t a_h[2][4], a_l[2][4];
#pragma unroll
            for (int i = 0; i < 2; i++) {
                uint32_t aaddr = aH + (wm * 32 + i * 16 + arow_off) * 80 + k16 * 32 + abyte;
                ldsm_x4(a_h[i], aaddr);
                ldsm_x4(a_l[i], aaddr + BUF_B);
            }
#pragma unroll
            for (int n16 = 0; n16 < 4; n16++) {
                uint32_t bh[4], bl[4];
                uint32_t baddr = bH + (wn * 64 + n16 * 16 + brow_off) * 80 + k16 * 32 + bbyte;
                ldsm_x4(bh, baddr);
                ldsm_x4(bl, baddr + BUF_B);
#pragma unroll
                for (int i = 0; i < 2; i++) {
                    mma16816(acc[i][2 * n16 + 0], a_h[i], bh[0], bh[1]);
                    mma16816(acc[i][2 * n16 + 0], a_h[i], bl[0], bl[1]);
                    mma16816(acc[i][2 * n16 + 0], a_l[i], bh[0], bh[1]);
                    mma16816(acc[i][2 * n16 + 1], a_h[i], bh[2], bh[3]);
                    mma16816(acc[i][2 * n16 + 1], a_h[i], bl[2], bl[3]);
                    mma16816(acc[i][2 * n16 + 1], a_l[i], bh[2], bh[3]);
                }
            }
        }
    }

    __syncthreads();

    float* outs = (float*)smem;
#pragma unroll
    for (int i = 0; i < 2; i++)
#pragma unroll
        for (int n8 = 0; n8 < 8; n8++) {
            int row = wm * 32 + i * 16 + g;
            int col = wn * 64 + n8 * 8 + 2 * tig;
            outs[row * OUT_LD + col + 0]       = acc[i][n8][0];
            outs[row * OUT_LD + col + 1]       = acc[i][n8][1];
            outs[(row + 8) * OUT_LD + col + 0] = acc[i][n8][2];
            outs[(row + 8) * OUT_LD + col + 1] = acc[i][n8][3];
        }
    __syncthreads();

#pragma unroll
    for (int i = 0; i < 16; i++) {
        int l   = t + i * 256;
        int row = l / 32;
        int c4  = l % 32;
        float4 bv4 = ((const float4*)(bias + n0))[c4];
        const float* sp = outs + row * OUT_LD + c4 * 4;
        float v0 = sp[0] + bv4.x;
        float v1 = sp[1] + bv4.y;
        float v2 = sp[2] + bv4.z;
        float v3 = sp[3] + bv4.w;
        __nv_bfloat16 h0 = __float2bfloat16_rn(v0);
        __nv_bfloat16 h1 = __float2bfloat16_rn(v1);
        __nv_bfloat16 h2 = __float2bfloat16_rn(v2);
        __nv_bfloat16 h3 = __float2bfloat16_rn(v3);
        __nv_bfloat162 hp0(h0, h1), hp1(h2, h3);
        __nv_bfloat162 lp0(__float2bfloat16_rn(v0 - __bfloat162float(h0)),
                           __float2bfloat16_rn(v1 - __bfloat162float(h1)));
        __nv_bfloat162 lp1(__float2bfloat16_rn(v2 - __bfloat162float(h2)),
                           __float2bfloat16_rn(v3 - __bfloat162float(h3)));
        size_t base = (size_t)(m0 + row) * EMB + n0 + c4 * 4;
        uint2 hu, lu;
        hu.x = *(uint32_t*)&hp0; hu.y = *(uint32_t*)&hp1;
        lu.x = *(uint32_t*)&lp0; lu.y = *(uint32_t*)&lp1;
        *(uint2*)(outh + base) = hu;
        *(uint2*)(outl + base) = lu;
    }
}

// ---------------------------------------------------------------------------
// FA2 attention, K AND V double-buffered, full-iteration prefetch lookahead.
// grid = (S/128, H, B), block = 256 (8 warps). Warp w: query rows w*16..+15.
// Iter kt: QK(kt) -> exp -> PV(kt) -> sync -> issue K/V(kt+2) -> wait(1) -> sync.
// smem: Q hi/lo [128][72]; K 2x{hi,lo}[64][72]; V 2x{hi,lo}[64][72] = 110592 B.
// ---------------------------------------------------------------------------
#define ATLD 72
#define ROWB (ATLD * 2)          // 144 bytes per row
#define AQH 0
#define AQL 18432
#define AK0 36864                // K stage s at AK0 + s*KSTG; lo at +KLO
#define KSTG 18432
#define KLO  9216
#define AV0  73728               // V stage s at AV0 + s*KSTG; lo at +KLO
#define ATT_SMEM_TOTAL 110592

__global__ __launch_bounds__(256) void attn_mma_kernel(float* __restrict__ out)
{
    extern __shared__ char sm[];
    const uint32_t sbase = smem_u32(sm);

    const int qt = blockIdx.x;
    const int h  = blockIdx.y;
    const int b  = blockIdx.z;

    const int t    = threadIdx.x;
    const int w    = t / 32;
    const int lane = t % 32;
    const int g    = lane >> 2;
    const int tig  = lane & 3;
    const int mrow = w * 16;

    const size_t qrow0 = (size_t)b * SEQ + qt * 128;
    const size_t krow0 = (size_t)b * SEQ;
    const __nv_bfloat16* __restrict__ gQh = g_qkvh + (size_t)0 * MROWS * EMB;
    const __nv_bfloat16* __restrict__ gQl = g_qkvl + (size_t)0 * MROWS * EMB;
    const __nv_bfloat16* __restrict__ gKh = g_qkvh + (size_t)1 * MROWS * EMB;
    const __nv_bfloat16* __restrict__ gKl = g_qkvl + (size_t)1 * MROWS * EMB;
    const __nv_bfloat16* __restrict__ gVh = g_qkvh + (size_t)2 * MROWS * EMB;
    const __nv_bfloat16* __restrict__ gVl = g_qkvl + (size_t)2 * MROWS * EMB;

    // per-thread load mappings
    const int qr0 = (t + 0)   / 8, qc0 = (t + 0)   % 8;
    const int qr1 = (t + 256) / 8, qc1 = (t + 256) % 8;
    const int qr2 = (t + 512) / 8, qc2 = (t + 512) % 8;
    const int qr3 = (t + 768) / 8, qc3 = (t + 768) % 8;
    const int kr0 = (t + 0)   / 8, kc0 = (t + 0)   % 8;
    const int kr1 = (t + 256) / 8, kc1 = (t + 256) % 8;

    // ---- prologue ----
    // group A: Q + K(0) + V(0)
    cpa16(sbase + AQH + qr0 * ROWB + qc0 * 16, gQh + (qrow0 + qr0) * EMB + h * HD + qc0 * 8);
    cpa16(sbase + AQH + qr1 * ROWB + qc1 * 16, gQh + (qrow0 + qr1) * EMB + h * HD + qc1 * 8);
    cpa16(sbase + AQH + qr2 * ROWB + qc2 * 16, gQh + (qrow0 + qr2) * EMB + h * HD + qc2 * 8);
    cpa16(sbase + AQH + qr3 * ROWB + qc3 * 16, gQh + (qrow0 + qr3) * EMB + h * HD + qc3 * 8);
    cpa16(sbase + AQL + qr0 * ROWB + qc0 * 16, gQl + (qrow0 + qr0) * EMB + h * HD + qc0 * 8);
    cpa16(sbase + AQL + qr1 * ROWB + qc1 * 16, gQl + (qrow0 + qr1) * EMB + h * HD + qc1 * 8);
    cpa16(sbase + AQL + qr2 * ROWB + qc2 * 16, gQl + (qrow0 + qr2) * EMB + h * HD + qc2 * 8);
    cpa16(sbase + AQL + qr3 * ROWB + qc3 * 16, gQl + (qrow0 + qr3) * EMB + h * HD + qc3 * 8);
    {
        size_t s0 = (krow0 + kr0) * EMB + h * HD + kc0 * 8;
        size_t s1 = (krow0 + kr1) * EMB + h * HD + kc1 * 8;
        cpa16(sbase + AK0 + kr0 * ROWB + kc0 * 16,       gKh + s0);
        cpa16(sbase + AK0 + kr1 * ROWB + kc1 * 16,       gKh + s1);
        cpa16(sbase + AK0 + KLO + kr0 * ROWB + kc0 * 16, gKl + s0);
        cpa16(sbase + AK0 + KLO + kr1 * ROWB + kc1 * 16, gKl + s1);
        cpa16(sbase + AV0 + kr0 * ROWB + kc0 * 16,       gVh + s0);
        cpa16(sbase + AV0 + kr1 * ROWB + kc1 * 16,       gVh + s1);
        cpa16(sbase + AV0 + KLO + kr0 * ROWB + kc0 * 16, gVl + s0);
        cpa16(sbase + AV0 + KLO + kr1 * ROWB + kc1 * 16, gVl + s1);
    }
    CP_COMMIT();
    // group B: K(1) + V(1)
    {
        size_t s0 = (krow0 + 64 + kr0) * EMB + h * HD + kc0 * 8;
        size_t s1 = (krow0 + 64 + kr1) * EMB + h * HD + kc1 * 8;
        cpa16(sbase + AK0 + KSTG + kr0 * ROWB + kc0 * 16,       gKh + s0);
        cpa16(sbase + AK0 + KSTG + kr1 * ROWB + kc1 * 16,       gKh + s1);
        cpa16(sbase + AK0 + KSTG + KLO + kr0 * ROWB + kc0 * 16, gKl + s0);
        cpa16(sbase + AK0 + KSTG + KLO + kr1 * ROWB + kc1 * 16, gKl + s1);
        cpa16(sbase + AV0 + KSTG + kr0 * ROWB + kc0 * 16,       gVh + s0);
        cpa16(sbase + AV0 + KSTG + kr1 * ROWB + kc1 * 16,       gVh + s1);
        cpa16(sbase + AV0 + KSTG + KLO + kr0 * ROWB + kc0 * 16, gVl + s0);
        cpa16(sbase + AV0 + KSTG + KLO + kr1 * ROWB + kc1 * 16, gVl + s1);
    }
    CP_COMMIT();
    CP_WAIT1();          // group A (Q,K0,V0) complete; B may be in flight
    __syncthreads();

    const int qrow_off = (lane & 7) + ((lane >> 3) & 1) * 8;
    const int qbyte    = (lane >> 4) * 16;
    const int krow_off = (lane & 7) + ((lane >> 4) & 1) * 8;
    const int kbyte    = ((lane >> 3) & 1) * 16;

    float oacc[8][4];
#pragma unroll
    for (int j = 0; j < 8; j++)
#pragma unroll
        for (int e = 0; e < 4; e++) oacc[j][e] = 0.0f;
    float lr0 = 0.0f, lr1 = 0.0f;

    const int NT = SEQ / 64;
    for (int kt = 0; kt < NT; kt++) {
        const uint32_t kbaseH = sbase + AK0 + (kt & 1) * KSTG;
        const uint32_t vbaseH = sbase + AV0 + (kt & 1) * KSTG;

        // ---- S = Q K^T (3-term split), S in registers ----
        float sacc[8][4];
#pragma unroll
        for (int j = 0; j < 8; j++)
#pragma unroll
            for (int e = 0; e < 4; e++) sacc[j][e] = 0.0f;

#pragma unroll
        for (int ks = 0; ks < 4; ks++) {
            uint32_t qa_h[4], qa_l[4];
            uint32_t qaddr = sbase + AQH + (mrow + qrow_off) * ROWB + ks * 32 + qbyte;
            ldsm_x4(qa_h, qaddr);
            ldsm_x4(qa_l, qaddr + (AQL - AQH));
#pragma unroll
            for (int n16 = 0; n16 < 4; n16++) {
                uint32_t bh[4], bl[4];
                uint32_t kaddr = kbaseH + (n16 * 16 + krow_off) * ROWB + ks * 32 + kbyte;
                ldsm_x4(bh, kaddr);
                ldsm_x4(bl, kaddr + KLO);
                mma16816(sacc[2 * n16 + 0], qa_h, bh[0], bh[1]);
                mma16816(sacc[2 * n16 + 0], qa_h, bl[0], bl[1]);
                mma16816(sacc[2 * n16 + 0], qa_l, bh[0], bh[1]);
                mma16816(sacc[2 * n16 + 1], qa_h, bh[2], bh[3]);
                mma16816(sacc[2 * n16 + 1], qa_h, bl[2], bl[3]);
                mma16816(sacc[2 * n16 + 1], qa_l, bh[2], bh[3]);
            }
        }

        // ---- exp + row sums (registers) ----
#pragma unroll
        for (int j = 0; j < 8; j++) {
            float p0 = __expf(sacc[j][0]);
            float p1 = __expf(sacc[j][1]);
            float p2 = __expf(sacc[j][2]);
            float p3 = __expf(sacc[j][3]);
            sacc[j][0] = p0; sacc[j][1] = p1; sacc[j][2] = p2; sacc[j][3] = p3;
            lr0 += p0 + p1;
            lr1 += p2 + p3;
        }

        // ---- O += P V (3-term split); V(kt) was prefetched a full iter ago ----
#pragma unroll
        for (int t16 = 0; t16 < 4; t16++) {
            uint32_t pah[4], pal[4];
            pah[0] = pack_hi(sacc[2 * t16][0], sacc[2 * t16][1]);
            pal[0] = pack_lo(sacc[2 * t16][0], sacc[2 * t16][1], pah[0]);
            pah[1] = pack_hi(sacc[2 * t16][2], sacc[2 * t16][3]);
            pal[1] = pack_lo(sacc[2 * t16][2], sacc[2 * t16][3], pah[1]);
            pah[2] = pack_hi(sacc[2 * t16 + 1][0], sacc[2 * t16 + 1][1]);
            pal[2] = pack_lo(sacc[2 * t16 + 1][0], sacc[2 * t16 + 1][1], pah[2]);
            pah[3] = pack_hi(sacc[2 * t16 + 1][2], sacc[2 * t16 + 1][3]);
            pal[3] = pack_lo(sacc[2 * t16 + 1][2], sacc[2 * t16 + 1][3], pah[3]);
#pragma unroll
            for (int n16 = 0; n16 < 4; n16++) {
                uint32_t vh[4], vl[4];
                uint32_t vaddr = vbaseH + (t16 * 16 + krow_off) * ROWB + n16 * 32 + kbyte;
                ldsm_x4_t(vh, vaddr);
                ldsm_x4_t(vl, vaddr + KLO);
                mma16816(oacc[2 * n16 + 0], pah, vh[0], vh[2]);
                mma16816(oacc[2 * n16 + 0], pah, vl[0], vl[2]);
                mma16816(oacc[2 * n16 + 0], pal, vh[0], vh[2]);
                mma16816(oacc[2 * n16 + 1], pah, vh[1], vh[3]);
                mma16816(oacc[2 * n16 + 1], pah, vl[1], vl[3]);
                mma16816(oacc[2 * n16 + 1], pal, vh[1], vh[3]);
            }
        }

        __syncthreads();   // all warps done reading stage kt&1

        // ---- issue K/V(kt+2) into the just-released stage ----
        if (kt + 2 < NT) {
            uint32_t ks = sbase + AK0 + (kt & 1) * KSTG;
            uint32_t vs = sbase + AV0 + (kt & 1) * KSTG;
            size_t s0 = (krow0 + (size_t)(kt + 2) * 64 + kr0) * EMB + h * HD + kc0 * 8;
            size_t s1 = (krow0 + (size_t)(kt + 2) * 64 + kr1) * EMB + h * HD + kc1 * 8;
            cpa16(ks + kr0 * ROWB + kc0 * 16,       gKh + s0);
            cpa16(ks + kr1 * ROWB + kc1 * 16,       gKh + s1);
            cpa16(ks + KLO + kr0 * ROWB + kc0 * 16, gKl + s0);
            cpa16(ks + KLO + kr1 * ROWB + kc1 * 16, gKl + s1);
            cpa16(vs + kr0 * ROWB + kc0 * 16,       gVh + s0);
            cpa16(vs + kr1 * ROWB + kc1 * 16,       gVh + s1);
            cpa16(vs + KLO + kr0 * ROWB + kc0 * 16, gVl + s0);
            cpa16(vs + KLO + kr1 * ROWB + kc1 * 16, gVl + s1);
            CP_COMMIT();
            CP_WAIT1();    // group (kt+1) complete; (kt+2) in flight
        } else {
            CP_WAIT0();    // drain remaining group(s)
        }
        __syncthreads();   // (kt+1) data visible to all
    }

    // ---- normalize + store ----
    lr0 += __shfl_xor_sync(0xffffffffu, lr0, 1);
    lr0 += __shfl_xor_sync(0xffffffffu, lr0, 2);
    lr1 += __shfl_xor_sync(0xffffffffu, lr1, 1);
    lr1 += __shfl_xor_sync(0xffffffffu, lr1, 2);
    const float inv0 = 1.0f / lr0;
    const float inv1 = 1.0f / lr1;

    const size_t row0 = (qrow0 + mrow + g) * EMB + h * HD;
    const size_t row1 = (qrow0 + mrow + g + 8) * EMB + h * HD;
#pragma unroll
    for (int j = 0; j < 8; j++) {
        float2 v0 = make_float2(oacc[j][0] * inv0, oacc[j][1] * inv0);
        float2 v1 = make_float2(oacc[j][2] * inv1, oacc[j][3] * inv1);
        *(float2*)(out + row0 + j * 8 + 2 * tig) = v0;
        *(float2*)(out + row1 + j * 8 + 2 * tig) = v1;
    }
}

// ---------------------------------------------------------------------------
extern "C" void kernel_launch(void* const* d_in, const int* in_sizes, int n_in,
                              void* d_out, int out_size)
{
    const float* x  = (const float*)d_in[0];
    const float* Wq = (const float*)d_in[1];
    const float* bq = (const float*)d_in[2];
    const float* Wk = (const float*)d_in[3];
    const float* bk = (const float*)d_in[4];
    const float* Wv = (const float*)d_in[5];
    const float* bv = (const float*)d_in[6];
    float* out = (float*)d_out;

    static bool attr_set = false;
    if (!attr_set) {
        cudaFuncSetAttribute(qkv_gemm_mma_kernel,
                             cudaFuncAttributeMaxDynamicSharedMemorySize, GT_SMEM_TOTAL);
        cudaFuncSetAttribute(attn_mma_kernel,
                             cudaFuncAttributeMaxDynamicSharedMemorySize, ATT_SMEM_TOTAL);
        attr_set = true;
    }

    split_x_kernel<<<2048, 256>>>(x);

    dim3 wgrid(EMB / 32, EMB / 32, 3);
    split_wt_kernel<<<wgrid, dim3(32, 8)>>>(Wq, Wk, Wv);

    dim3 ggrid(EMB / 128, MROWS / 128, 3);
    qkv_gemm_mma_kernel<<<ggrid, 256, GT_SMEM_TOTAL>>>(bq, bk, bv);

    dim3 agrid(SEQ / 128, NH, BSZ);
    attn_mma_kernel<<<agrid, 256, ATT_SMEM_TOTAL>>>(out);
}

// round 17
// speedup vs baseline: 1.0327x; 1.0327x over previous
#include <cuda_runtime.h>
#include <cuda_bf16.h>
#include <cstdint>

#define BSZ 2
#define SEQ 2048
#define EMB 1024
#define NH  16
#define HD  64
#define MROWS (BSZ*SEQ)   // 4096

// ---------------------------------------------------------------------------
// Global scratch
// ---------------------------------------------------------------------------
__device__ __nv_bfloat16 g_xh[(size_t)MROWS * EMB];              // x split hi
__device__ __nv_bfloat16 g_xl[(size_t)MROWS * EMB];              // x split lo
__device__ __nv_bfloat16 g_wth[(size_t)3 * EMB * EMB];           // W^T split hi  [which][n][k]
__device__ __nv_bfloat16 g_wtl[(size_t)3 * EMB * EMB];           // W^T split lo
__device__ __nv_bfloat16 g_qkvh[(size_t)3 * MROWS * EMB];        // Q,K,V bf16 hi
__device__ __nv_bfloat16 g_qkvl[(size_t)3 * MROWS * EMB];        // Q,K,V bf16 lo

// ---------------------------------------------------------------------------
// PTX helpers
// ---------------------------------------------------------------------------
__device__ __forceinline__ uint32_t smem_u32(const void* p) {
    uint32_t a;
    asm("{ .reg .u64 t; cvta.to.shared.u64 t, %1; cvt.u32.u64 %0, t; }" : "=r"(a) : "l"(p));
    return a;
}
__device__ __forceinline__ void ldsm_x4(uint32_t* r, uint32_t addr) {
    asm volatile("ldmatrix.sync.aligned.m8n8.x4.shared.b16 {%0,%1,%2,%3}, [%4];"
                 : "=r"(r[0]), "=r"(r[1]), "=r"(r[2]), "=r"(r[3]) : "r"(addr));
}
__device__ __forceinline__ void ldsm_x4_t(uint32_t* r, uint32_t addr) {
    asm volatile("ldmatrix.sync.aligned.m8n8.x4.trans.shared.b16 {%0,%1,%2,%3}, [%4];"
                 : "=r"(r[0]), "=r"(r[1]), "=r"(r[2]), "=r"(r[3]) : "r"(addr));
}
__device__ __forceinline__ void mma16816(float* c, const uint32_t* a, uint32_t b0, uint32_t b1) {
    asm volatile("mma.sync.aligned.m16n8k16.row.col.f32.bf16.bf16.f32 "
                 "{%0,%1,%2,%3}, {%4,%5,%6,%7}, {%8,%9}, {%0,%1,%2,%3};"
                 : "+f"(c[0]), "+f"(c[1]), "+f"(c[2]), "+f"(c[3])
                 : "r"(a[0]), "r"(a[1]), "r"(a[2]), "r"(a[3]), "r"(b0), "r"(b1));
}
__device__ __forceinline__ void cpa16(uint32_t s, const void* g) {
    asm volatile("cp.async.cg.shared.global [%0], [%1], 16;" :: "r"(s), "l"(g));
}
#define CP_COMMIT() asm volatile("cp.async.commit_group;" ::: "memory")
#define CP_WAIT0()  asm volatile("cp.async.wait_group 0;" ::: "memory")

__device__ __forceinline__ uint32_t pack_hi(float x, float y) {
    __nv_bfloat162 t(__float2bfloat16_rn(x), __float2bfloat16_rn(y));
    return *(uint32_t*)&t;
}
__device__ __forceinline__ uint32_t pack_lo(float x, float y, uint32_t hi) {
    __nv_bfloat162 hv = *(__nv_bfloat162*)&hi;
    __nv_bfloat162 t(__float2bfloat16_rn(x - __bfloat162float(hv.x)),
                     __float2bfloat16_rn(y - __bfloat162float(hv.y)));
    return *(uint32_t*)&t;
}

// ---------------------------------------------------------------------------
// Fused split kernel: grid (32, 32, 4), block 256.
//   z < 3 : W^T transpose + split for which=z (32x32 tile at (x,y))
//   z == 3: x split; slab index s = y*32 + x in [0,1024): 1024 float4 each
// ---------------------------------------------------------------------------
__global__ __launch_bounds__(256) void split_fused_kernel(
    const float* __restrict__ x,
    const float* __restrict__ Wq, const float* __restrict__ Wk, const float* __restrict__ Wv)
{
    const int which = blockIdx.z;

    if (which < 3) {
        const float* __restrict__ W = (which == 0) ? Wq : ((which == 1) ? Wk : Wv);
        __shared__ float tile[32][33];

        const int tx = threadIdx.x % 32;
        const int ty = threadIdx.x / 32;   // 0..7
        const int nt = blockIdx.x, kt = blockIdx.y;

#pragma unroll
        for (int i = 0; i < 4; i++) {
            int k = kt * 32 + ty + i * 8;
            tile[ty + i * 8][tx] = W[(size_t)k * EMB + nt * 32 + tx];
        }
        __syncthreads();

        const size_t base = (size_t)which * EMB * EMB;
#pragma unroll
        for (int i = 0; i < 4; i++) {
            int n = nt * 32 + ty + i * 8;
            int k = kt * 32 + tx;
            float v = tile[tx][ty + i * 8];
            __nv_bfloat16 hh = __float2bfloat16_rn(v);
            __nv_bfloat16 ll = __float2bfloat16_rn(v - __bfloat162float(hh));
            g_wth[base + (size_t)n * EMB + k] = hh;
            g_wtl[base + (size_t)n * EMB + k] = ll;
        }
    } else {
        // x split: 1M float4 granules over 1024 blocks -> 4096 per block, 16/thread? no:
        // slab = 1024 granules per block, 4 per thread
        const size_t slab = (size_t)(blockIdx.y * 32 + blockIdx.x) * 1024;
        const float4* __restrict__ x4 = (const float4*)x;
#pragma unroll
        for (int i = 0; i < 4; i++) {
            size_t idx = slab + threadIdx.x + i * 256;
            float4 v = x4[idx];
            __nv_bfloat16 h0 = __float2bfloat16_rn(v.x);
            __nv_bfloat16 h1 = __float2bfloat16_rn(v.y);
            __nv_bfloat16 h2 = __float2bfloat16_rn(v.z);
            __nv_bfloat16 h3 = __float2bfloat16_rn(v.w);
            __nv_bfloat16 l0 = __float2bfloat16_rn(v.x - __bfloat162float(h0));
            __nv_bfloat16 l1 = __float2bfloat16_rn(v.y - __bfloat162float(h1));
            __nv_bfloat16 l2 = __float2bfloat16_rn(v.z - __bfloat162float(h2));
            __nv_bfloat16 l3 = __float2bfloat16_rn(v.w - __bfloat162float(h3));
            __nv_bfloat162* ph = (__nv_bfloat162*)&g_xh[idx * 4];
            __nv_bfloat162* pl = (__nv_bfloat162*)&g_xl[idx * 4];
            ph[0] = __nv_bfloat162(h0, h1); ph[1] = __nv_bfloat162(h2, h3);
            pl[0] = __nv_bfloat162(l0, l1); pl[1] = __nv_bfloat162(l2, l3);
        }
    }
}

// ---------------------------------------------------------------------------
// Raw-mma QKV GEMM with cp.async 2-stage pipeline (R12 known-good).
// ---------------------------------------------------------------------------
#define TLD 40                      // smem row stride (elements); 80 bytes
#define BUF_B (128 * TLD * 2)       // 10240 bytes per buffer
#define STAGE_B (4 * BUF_B)         // 40960 per stage
#define OUT_LD 132
#define GT_SMEM_TOTAL (2 * STAGE_B) // 81920

__global__ __launch_bounds__(256) void qkv_gemm_mma_kernel(
    const float* __restrict__ bq, const float* __restrict__ bk, const float* __restrict__ bv)
{
    extern __shared__ char smem[];
    const uint32_t sb = smem_u32(smem);

    const int which = blockIdx.z;
    const int n0 = blockIdx.x * 128;
    const int m0 = blockIdx.y * 128;
    const float* __restrict__ bias = (which == 0) ? bq : ((which == 1) ? bk : bv);
    __nv_bfloat16* __restrict__ outh = g_qkvh + (size_t)which * MROWS * EMB;
    __nv_bfloat16* __restrict__ outl = g_qkvl + (size_t)which * MROWS * EMB;

    const int t    = threadIdx.x;
    const int w    = t / 32;
    const int lane = t % 32;
    const int wm   = w % 4;
    const int wn   = w / 4;
    const int g    = lane >> 2;
    const int tig  = lane & 3;

    const __nv_bfloat16* __restrict__ srcAh = g_xh + (size_t)m0 * EMB;
    const __nv_bfloat16* __restrict__ srcAl = g_xl + (size_t)m0 * EMB;
    const __nv_bfloat16* __restrict__ srcBh = g_wth + (size_t)which * EMB * EMB + (size_t)n0 * EMB;
    const __nv_bfloat16* __restrict__ srcBl = g_wtl + (size_t)which * EMB * EMB + (size_t)n0 * EMB;

    const int arow_off = (lane & 7) + ((lane >> 3) & 1) * 8;
    const int abyte    = (lane >> 4) * 16;
    const int brow_off = (lane & 7) + ((lane >> 4) & 1) * 8;
    const int bbyte    = ((lane >> 3) & 1) * 16;

    const int lrow0 = (t + 0)   / 4, lc0 = (t + 0)   % 4;
    const int lrow1 = (t + 256) / 4, lc1 = (t + 256) % 4;

    float acc[2][8][4];
#pragma unroll
    for (int i = 0; i < 2; i++)
#pragma unroll
        for (int j = 0; j < 8; j++)
#pragma unroll
            for (int e = 0; e < 4; e++) acc[i][j][e] = 0.0f;

    {
        uint32_t s0 = sb;
        cpa16(s0 + 0 * BUF_B + lrow0 * 80 + lc0 * 16, srcAh + (size_t)lrow0 * EMB + lc0 * 8);
        cpa16(s0 + 0 * BUF_B + lrow1 * 80 + lc1 * 16, srcAh + (size_t)lrow1 * EMB + lc1 * 8);
        cpa16(s0 + 1 * BUF_B + lrow0 * 80 + lc0 * 16, srcAl + (size_t)lrow0 * EMB + lc0 * 8);
        cpa16(s0 + 1 * BUF_B + lrow1 * 80 + lc1 * 16, srcAl + (size_t)lrow1 * EMB + lc1 * 8);
        cpa16(s0 + 2 * BUF_B + lrow0 * 80 + lc0 * 16, srcBh + (size_t)lrow0 * EMB + lc0 * 8);
        cpa16(s0 + 2 * BUF_B + lrow1 * 80 + lc1 * 16, srcBh + (size_t)lrow1 * EMB + lc1 * 8);
        cpa16(s0 + 3 * BUF_B + lrow0 * 80 + lc0 * 16, srcBl + (size_t)lrow0 * EMB + lc0 * 8);
        cpa16(s0 + 3 * BUF_B + lrow1 * 80 + lc1 * 16, srcBl + (size_t)lrow1 * EMB + lc1 * 8);
        CP_COMMIT();
    }

    for (int kc32 = 0; kc32 < EMB / 32; kc32++) {
        CP_WAIT0();
        __syncthreads();

        if (kc32 + 1 < EMB / 32) {
            const int kc = (kc32 + 1) * 32;
            uint32_t s1 = sb + ((kc32 + 1) & 1) * STAGE_B;
            cpa16(s1 + 0 * BUF_B + lrow0 * 80 + lc0 * 16, srcAh + (size_t)lrow0 * EMB + kc + lc0 * 8);
            cpa16(s1 + 0 * BUF_B + lrow1 * 80 + lc1 * 16, srcAh + (size_t)lrow1 * EMB + kc + lc1 * 8);
            cpa16(s1 + 1 * BUF_B + lrow0 * 80 + lc0 * 16, srcAl + (size_t)lrow0 * EMB + kc + lc0 * 8);
            cpa16(s1 + 1 * BUF_B + lrow1 * 80 + lc1 * 16, srcAl + (size_t)lrow1 * EMB + kc + lc1 * 8);
            cpa16(s1 + 2 * BUF_B + lrow0 * 80 + lc0 * 16, srcBh + (size_t)lrow0 * EMB + kc + lc0 * 8);
            cpa16(s1 + 2 * BUF_B + lrow1 * 80 + lc1 * 16, srcBh + (size_t)lrow1 * EMB + kc + lc1 * 8);
            cpa16(s1 + 3 * BUF_B + lrow0 * 80 + lc0 * 16, srcBl + (size_t)lrow0 * EMB + kc + lc0 * 8);
            cpa16(s1 + 3 * BUF_B + lrow1 * 80 + lc1 * 16, srcBl + (size_t)lrow1 * EMB + kc + lc1 * 8);
            CP_COMMIT();
        }

        const uint32_t st = sb + (kc32 & 1) * STAGE_B;
        const uint32_t aH = st + 0 * BUF_B;
        const uint32_t bH = st + 2 * BUF_B;

#pragma unroll
        for (int k16 = 0; k16 < 2; k16++) {
            uint32_t a_h[2][4], a_l[2][4];
#pragma unroll
            for (int i = 0; i < 2; i++) {
                uint32_t aaddr = aH + (wm * 32 + i * 16 + arow_off) * 80 + k16 * 32 + abyte;
                ldsm_x4(a_h[i], aaddr);
                ldsm_x4(a_l[i], aaddr + BUF_B);
            }
#pragma unroll
            for (int n16 = 0; n16 < 4; n16++) {
                uint32_t bh[4], bl[4];
                uint32_t baddr = bH + (wn * 64 + n16 * 16 + brow_off) * 80 + k16 * 32 + bbyte;
                ldsm_x4(bh, baddr);
                ldsm_x4(bl, baddr + BUF_B);
#pragma unroll
                for (int i = 0; i < 2; i++) {
                    mma16816(acc[i][2 * n16 + 0], a_h[i], bh[0], bh[1]);
                    mma16816(acc[i][2 * n16 + 0], a_h[i], bl[0], bl[1]);
                    mma16816(acc[i][2 * n16 + 0], a_l[i], bh[0], bh[1]);
                    mma16816(acc[i][2 * n16 + 1], a_h[i], bh[2], bh[3]);
                    mma16816(acc[i][2 * n16 + 1], a_h[i], bl[2], bl[3]);
                    mma16816(acc[i][2 * n16 + 1], a_l[i], bh[2], bh[3]);
                }
            }
        }
    }

    __syncthreads();

    float* outs = (float*)smem;
#pragma unroll
    for (int i = 0; i < 2; i++)
#pragma unroll
        for (int n8 = 0; n8 < 8; n8++) {
            int row = wm * 32 + i * 16 + g;
            int col = wn * 64 + n8 * 8 + 2 * tig;
            outs[row * OUT_LD + col + 0]       = acc[i][n8][0];
            outs[row * OUT_LD + col + 1]       = acc[i][n8][1];
            outs[(row + 8) * OUT_LD + col + 0] = acc[i][n8][2];
            outs[(row + 8) * OUT_LD + col + 1] = acc[i][n8][3];
        }
    __syncthreads();

#pragma unroll
    for (int i = 0; i < 16; i++) {
        int l   = t + i * 256;
        int row = l / 32;
        int c4  = l % 32;
        float4 bv4 = ((const float4*)(bias + n0))[c4];
        const float* sp = outs + row * OUT_LD + c4 * 4;
        float v0 = sp[0] + bv4.x;
        float v1 = sp[1] + bv4.y;
        float v2 = sp[2] + bv4.z;
        float v3 = sp[3] + bv4.w;
        __nv_bfloat16 h0 = __float2bfloat16_rn(v0);
        __nv_bfloat16 h1 = __float2bfloat16_rn(v1);
        __nv_bfloat16 h2 = __float2bfloat16_rn(v2);
        __nv_bfloat16 h3 = __float2bfloat16_rn(v3);
        __nv_bfloat162 hp0(h0, h1), hp1(h2, h3);
        __nv_bfloat162 lp0(__float2bfloat16_rn(v0 - __bfloat162float(h0)),
                           __float2bfloat16_rn(v1 - __bfloat162float(h1)));
        __nv_bfloat162 lp1(__float2bfloat16_rn(v2 - __bfloat162float(h2)),
                           __float2bfloat16_rn(v3 - __bfloat162float(h3)));
        size_t base = (size_t)(m0 + row) * EMB + n0 + c4 * 4;
        uint2 hu, lu;
        hu.x = *(uint32_t*)&hp0; hu.y = *(uint32_t*)&hp1;
        lu.x = *(uint32_t*)&lp0; lu.y = *(uint32_t*)&lp1;
        *(uint2*)(outh + base) = hu;
        *(uint2*)(outl + base) = lu;
    }
}

// ---------------------------------------------------------------------------
// FA2 attention (R13 known-good): cp.async K/V pipeline, K double-buffered,
// V single-buffered. grid = (S/128, H, B), block = 256 (8 warps).
// Per iter t: issue V(t)+K(t+1) -> QK(t) (overlaps loads) -> wait+barrier ->
// PV(t) -> barrier.
// ---------------------------------------------------------------------------
#define ATLD 72
#define ROWB (ATLD * 2)          // 144 bytes per row
#define AQH 0
#define AQL 18432
#define AK0 36864                // K stage s at AK0 + s*18432; lo at +9216
#define KSTG 18432
#define KLO  9216
#define AV   73728               // V hi; lo at +9216
#define ATT_SMEM_TOTAL 92160

__global__ __launch_bounds__(256) void attn_mma_kernel(float* __restrict__ out)
{
    extern __shared__ char sm[];
    const uint32_t sbase = smem_u32(sm);

    const int qt = blockIdx.x;
    const int h  = blockIdx.y;
    const int b  = blockIdx.z;

    const int t    = threadIdx.x;
    const int w    = t / 32;
    const int lane = t % 32;
    const int g    = lane >> 2;
    const int tig  = lane & 3;
    const int mrow = w * 16;

    const size_t qrow0 = (size_t)b * SEQ + qt * 128;
    const size_t krow0 = (size_t)b * SEQ;
    const __nv_bfloat16* __restrict__ gQh = g_qkvh + (size_t)0 * MROWS * EMB;
    const __nv_bfloat16* __restrict__ gQl = g_qkvl + (size_t)0 * MROWS * EMB;
    const __nv_bfloat16* __restrict__ gKh = g_qkvh + (size_t)1 * MROWS * EMB;
    const __nv_bfloat16* __restrict__ gKl = g_qkvl + (size_t)1 * MROWS * EMB;
    const __nv_bfloat16* __restrict__ gVh = g_qkvh + (size_t)2 * MROWS * EMB;
    const __nv_bfloat16* __restrict__ gVl = g_qkvl + (size_t)2 * MROWS * EMB;

    // per-thread load mappings
    const int qr0 = (t + 0)   / 8, qc0 = (t + 0)   % 8;
    const int qr1 = (t + 256) / 8, qc1 = (t + 256) % 8;
    const int qr2 = (t + 512) / 8, qc2 = (t + 512) % 8;
    const int qr3 = (t + 768) / 8, qc3 = (t + 768) % 8;
    const int kr0 = (t + 0)   / 8, kc0 = (t + 0)   % 8;
    const int kr1 = (t + 256) / 8, kc1 = (t + 256) % 8;

    // ---- prologue: async-load Q (hi+lo) and K(0) into stage 0 ----
    cpa16(sbase + AQH + qr0 * ROWB + qc0 * 16, gQh + (qrow0 + qr0) * EMB + h * HD + qc0 * 8);
    cpa16(sbase + AQH + qr1 * ROWB + qc1 * 16, gQh + (qrow0 + qr1) * EMB + h * HD + qc1 * 8);
    cpa16(sbase + AQH + qr2 * ROWB + qc2 * 16, gQh + (qrow0 + qr2) * EMB + h * HD + qc2 * 8);
    cpa16(sbase + AQH + qr3 * ROWB + qc3 * 16, gQh + (qrow0 + qr3) * EMB + h * HD + qc3 * 8);
    cpa16(sbase + AQL + qr0 * ROWB + qc0 * 16, gQl + (qrow0 + qr0) * EMB + h * HD + qc0 * 8);
    cpa16(sbase + AQL + qr1 * ROWB + qc1 * 16, gQl + (qrow0 + qr1) * EMB + h * HD + qc1 * 8);
    cpa16(sbase + AQL + qr2 * ROWB + qc2 * 16, gQl + (qrow0 + qr2) * EMB + h * HD + qc2 * 8);
    cpa16(sbase + AQL + qr3 * ROWB + qc3 * 16, gQl + (qrow0 + qr3) * EMB + h * HD + qc3 * 8);
    cpa16(sbase + AK0 + kr0 * ROWB + kc0 * 16,       gKh + (krow0 + kr0) * EMB + h * HD + kc0 * 8);
    cpa16(sbase + AK0 + kr1 * ROWB + kc1 * 16,       gKh + (krow0 + kr1) * EMB + h * HD + kc1 * 8);
    cpa16(sbase + AK0 + KLO + kr0 * ROWB + kc0 * 16, gKl + (krow0 + kr0) * EMB + h * HD + kc0 * 8);
    cpa16(sbase + AK0 + KLO + kr1 * ROWB + kc1 * 16, gKl + (krow0 + kr1) * EMB + h * HD + kc1 * 8);
    CP_COMMIT();
    CP_WAIT0();
    __syncthreads();

    const int qrow_off = (lane & 7) + ((lane >> 3) & 1) * 8;
    const int qbyte    = (lane >> 4) * 16;
    const int krow_off = (lane & 7) + ((lane >> 4) & 1) * 8;
    const int kbyte    = ((lane >> 3) & 1) * 16;

    float oacc[8][4];
#pragma unroll
    for (int j = 0; j < 8; j++)
#pragma unroll
        for (int e = 0; e < 4; e++) oacc[j][e] = 0.0f;
    float lr0 = 0.0f, lr1 = 0.0f;

    for (int kt = 0; kt < SEQ / 64; kt++) {
        // ---- issue V(kt) and K(kt+1) async (overlap with QK below) ----
        {
            size_t vsrc0 = (krow0 + (size_t)kt * 64 + kr0) * EMB + h * HD + kc0 * 8;
            size_t vsrc1 = (krow0 + (size_t)kt * 64 + kr1) * EMB + h * HD + kc1 * 8;
            cpa16(sbase + AV + kr0 * ROWB + kc0 * 16,       gVh + vsrc0);
            cpa16(sbase + AV + kr1 * ROWB + kc1 * 16,       gVh + vsrc1);
            cpa16(sbase + AV + KLO + kr0 * ROWB + kc0 * 16, gVl + vsrc0);
            cpa16(sbase + AV + KLO + kr1 * ROWB + kc1 * 16, gVl + vsrc1);
            if (kt + 1 < SEQ / 64) {
                uint32_t ks = sbase + AK0 + ((kt + 1) & 1) * KSTG;
                size_t ksrc0 = (krow0 + (size_t)(kt + 1) * 64 + kr0) * EMB + h * HD + kc0 * 8;
                size_t ksrc1 = (krow0 + (size_t)(kt + 1) * 64 + kr1) * EMB + h * HD + kc1 * 8;
                cpa16(ks + kr0 * ROWB + kc0 * 16,       gKh + ksrc0);
                cpa16(ks + kr1 * ROWB + kc1 * 16,       gKh + ksrc1);
                cpa16(ks + KLO + kr0 * ROWB + kc0 * 16, gKl + ksrc0);
                cpa16(ks + KLO + kr1 * ROWB + kc1 * 16, gKl + ksrc1);
            }
            CP_COMMIT();
        }

        // ---- S = Q K^T (3-term split) on K stage kt&1 ----
        const uint32_t kbaseH = sbase + AK0 + (kt & 1) * KSTG;
        float sacc[8][4];
#pragma unroll
        for (int j = 0; j < 8; j++)
#pragma unroll
            for (int e = 0; e < 4; e++) sacc[j][e] = 0.0f;

#pragma unroll
        for (int ks = 0; ks < 4; ks++) {
            uint32_t qa_h[4], qa_l[4];
            uint32_t qaddr = sbase + AQH + (mrow + qrow_off) * ROWB + ks * 32 + qbyte;
            ldsm_x4(qa_h, qaddr);
            ldsm_x4(qa_l, qaddr + (AQL - AQH));
#pragma unroll
            for (int n16 = 0; n16 < 4; n16++) {
                uint32_t bh[4], bl[4];
                uint32_t kaddr = kbaseH + (n16 * 16 + krow_off) * ROWB + ks * 32 + kbyte;
                ldsm_x4(bh, kaddr);
                ldsm_x4(bl, kaddr + KLO);
                mma16816(sacc[2 * n16 + 0], qa_h, bh[0], bh[1]);
                mma16816(sacc[2 * n16 + 0], qa_h, bl[0], bl[1]);
                mma16816(sacc[2 * n16 + 0], qa_l, bh[0], bh[1]);
                mma16816(sacc[2 * n16 + 1], qa_h, bh[2], bh[3]);
                mma16816(sacc[2 * n16 + 1], qa_h, bl[2], bl[3]);
                mma16816(sacc[2 * n16 + 1], qa_l, bh[2], bh[3]);
            }
        }

        // ---- exp + row sums (registers) ----
#pragma unroll
        for (int j = 0; j < 8; j++) {
            float p0 = __expf(sacc[j][0]);
            float p1 = __expf(sacc[j][1]);
            float p2 = __expf(sacc[j][2]);
            float p3 = __expf(sacc[j][3]);
            sacc[j][0] = p0; sacc[j][1] = p1; sacc[j][2] = p2; sacc[j][3] = p3;
            lr0 += p0 + p1;
            lr1 += p2 + p3;
        }

        // ---- wait V(kt) (and K(kt+1)); make visible ----
        CP_WAIT0();
        __syncthreads();

        // ---- O += P V (3-term split) ----
#pragma unroll
        for (int t16 = 0; t16 < 4; t16++) {
            uint32_t pah[4], pal[4];
            pah[0] = pack_hi(sacc[2 * t16][0], sacc[2 * t16][1]);
            pal[0] = pack_lo(sacc[2 * t16][0], sacc[2 * t16][1], pah[0]);
            pah[1] = pack_hi(sacc[2 * t16][2], sacc[2 * t16][3]);
            pal[1] = pack_lo(sacc[2 * t16][2], sacc[2 * t16][3], pah[1]);
            pah[2] = pack_hi(sacc[2 * t16 + 1][0], sacc[2 * t16 + 1][1]);
            pal[2] = pack_lo(sacc[2 * t16 + 1][0], sacc[2 * t16 + 1][1], pah[2]);
            pah[3] = pack_hi(sacc[2 * t16 + 1][2], sacc[2 * t16 + 1][3]);
            pal[3] = pack_lo(sacc[2 * t16 + 1][2], sacc[2 * t16 + 1][3], pah[3]);
#pragma unroll
            for (int n16 = 0; n16 < 4; n16++) {
                uint32_t vh[4], vl[4];
                uint32_t vaddr = sbase + AV + (t16 * 16 + krow_off) * ROWB + n16 * 32 + kbyte;
                ldsm_x4_t(vh, vaddr);
                ldsm_x4_t(vl, vaddr + KLO);
                mma16816(oacc[2 * n16 + 0], pah, vh[0], vh[2]);
                mma16816(oacc[2 * n16 + 0], pah, vl[0], vl[2]);
                mma16816(oacc[2 * n16 + 0], pal, vh[0], vh[2]);
                mma16816(oacc[2 * n16 + 1], pah, vh[1], vh[3]);
                mma16816(oacc[2 * n16 + 1], pah, vl[1], vl[3]);
                mma16816(oacc[2 * n16 + 1], pal, vh[1], vh[3]);
            }
        }
        __syncthreads();   // PV reads done before next iter's V issue
    }

    // ---- normalize + store ----
    lr0 += __shfl_xor_sync(0xffffffffu, lr0, 1);
    lr0 += __shfl_xor_sync(0xffffffffu, lr0, 2);
    lr1 += __shfl_xor_sync(0xffffffffu, lr1, 1);
    lr1 += __shfl_xor_sync(0xffffffffu, lr1, 2);
    const float inv0 = 1.0f / lr0;
    const float inv1 = 1.0f / lr1;

    const size_t row0 = (qrow0 + mrow + g) * EMB + h * HD;
    const size_t row1 = (qrow0 + mrow + g + 8) * EMB + h * HD;
#pragma unroll
    for (int j = 0; j < 8; j++) {
        float2 v0 = make_float2(oacc[j][0] * inv0, oacc[j][1] * inv0);
        float2 v1 = make_float2(oacc[j][2] * inv1, oacc[j][3] * inv1);
        *(float2*)(out + row0 + j * 8 + 2 * tig) = v0;
        *(float2*)(out + row1 + j * 8 + 2 * tig) = v1;
    }
}

// ---------------------------------------------------------------------------
extern "C" void kernel_launch(void* const* d_in, const int* in_sizes, int n_in,
                              void* d_out, int out_size)
{
    const float* x  = (const float*)d_in[0];
    const float* Wq = (const float*)d_in[1];
    const float* bq = (const float*)d_in[2];
    const float* Wk = (const float*)d_in[3];
    const float* bk = (const float*)d_in[4];
    const float* Wv = (const float*)d_in[5];
    const float* bv = (const float*)d_in[6];
    float* out = (float*)d_out;

    static bool attr_set = false;
    if (!attr_set) {
        cudaFuncSetAttribute(qkv_gemm_mma_kernel,
                             cudaFuncAttributeMaxDynamicSharedMemorySize, GT_SMEM_TOTAL);
        cudaFuncSetAttribute(attn_mma_kernel,
                             cudaFuncAttributeMaxDynamicSharedMemorySize, ATT_SMEM_TOTAL);
        attr_set = true;
    }

    dim3 sgrid(32, 32, 4);
    split_fused_kernel<<<sgrid, 256>>>(x, Wq, Wk, Wv);

    dim3 ggrid(EMB / 128, MROWS / 128, 3);
    qkv_gemm_mma_kernel<<<ggrid, 256, GT_SMEM_TOTAL>>>(bq, bk, bv);

    dim3 agrid(SEQ / 128, NH, BSZ);
    attn_mma_kernel<<<agrid, 256, ATT_SMEM_TOTAL>>>(out);
}